// round 17
// baseline (speedup 1.0000x reference)
#include <cuda_runtime.h>
#include <math.h>

// Problem constants (fixed by the reference's setup)
#define N_IN 1000000
#define M_NODES 2000000
#define S0 (2 * N_IN + 2)

// Scratch (no cudaMalloc allowed): encoded input + two ping-pong M-buffers
__device__ float g_enc[S0];
__device__ float g_bufA[M_NODES];
__device__ float g_bufB[M_NODES];

// log(1 - exp(x)) for x <= 0, stable (Maechler 2012), matching reference
__device__ __forceinline__ float log1mexp_f(float x) {
    const float NLOG2 = -0.69314718056f;
    if (x > NLOG2) {
        return logf(-expm1f(x));     // x in (-log2, 0]; x=0 -> log(0) = -inf
    } else {
        return log1pf(-expf(x));
    }
}

// encode: pos/neg pair per input is adjacent in g_enc -> single float2 store.
__global__ void __launch_bounds__(512) encode_kernel(const float* __restrict__ pos) {
    int i = blockIdx.x * blockDim.x + threadIdx.x;
    if (i == 0) {
        g_enc[0] = -INFINITY;  // literal False
        g_enc[1] = 0.0f;       // literal True
    }
    if (i < N_IN) {
        float p = __ldcs(pos + i);
        float2 pn = make_float2(p, log1mexp_f(p));
        __stcg(reinterpret_cast<float2*>(g_enc + 2) + i, pn);
    }
}

// Gather with L1-bypass: random 4B gathers have ~3% L1 hit rate; skip the fill.
__device__ __forceinline__ float gcg(const float* p) { return __ldcg(p); }

// product layer: out[m] = sum of 4 gathered log-probs.
// Two-wave grid-stride with 2-stage ptr pipeline (champion config, best
// measured 132.0us total). Next iteration's ptr int4 is in DRAM flight while
// this iteration's gathers (L2) are serviced; the second wave restores
// retirement-driven SM load rebalancing.
// (Falsified across R1-R16: ILP>1, L2 prefetch, PDL, 1/3-wave, mixed waves,
//  256-thr granularity — all neutral or worse. L1tex wavefront floor ~78%.)
__global__ void __launch_bounds__(512) product_kernel(
        const float* __restrict__ src,
        const int4* __restrict__ ptrs,
        float* __restrict__ dst) {
    const int stride = gridDim.x * blockDim.x;
    int m = blockIdx.x * blockDim.x + threadIdx.x;
    if (m >= M_NODES) return;
    int4 p = __ldcs(ptrs + m);
    while (true) {
        int mn = m + stride;
        int4 pn;
        if (mn < M_NODES) pn = __ldcs(ptrs + mn);   // prefetch next ptrs
        float a = gcg(src + p.x);
        float b = gcg(src + p.y);
        float c = gcg(src + p.z);
        float d = gcg(src + p.w);
        __stcg(dst + m, (a + b) + (c + d));
        if (mn >= M_NODES) break;
        m = mn; p = pn;
    }
}

// sum layer: 4-way logsumexp with 1e-15 floor, max detached. Same pipeline.
__global__ void __launch_bounds__(512) sum_kernel(
        const float* __restrict__ src,
        const int4* __restrict__ ptrs,
        float* __restrict__ dst) {
    const int stride = gridDim.x * blockDim.x;
    int m = blockIdx.x * blockDim.x + threadIdx.x;
    if (m >= M_NODES) return;
    int4 p = __ldcs(ptrs + m);
    while (true) {
        int mn = m + stride;
        int4 pn;
        if (mn < M_NODES) pn = __ldcs(ptrs + mn);
        float a = gcg(src + p.x);
        float b = gcg(src + p.y);
        float c = gcg(src + p.z);
        float d = gcg(src + p.w);
        float mx = fmaxf(fmaxf(a, b), fmaxf(c, d));
        float out;
        if (mx == -INFINITY) {
            out = -INFINITY;            // reference nan_to_num path
        } else {
            float s = __expf(a - mx) + __expf(b - mx)
                    + __expf(c - mx) + __expf(d - mx);
            out = __logf(s + 1e-15f) + mx;
        }
        __stcg(dst + m, out);
        if (mn >= M_NODES) break;
        m = mn; p = pn;
    }
}

extern "C" void kernel_launch(void* const* d_in, const int* in_sizes, int n_in,
                              void* d_out, int out_size) {
    const float* pos   = (const float*)d_in[0];
    const int4*  ptrs0 = (const int4*)d_in[1];
    const int4*  ptrs1 = (const int4*)d_in[2];
    const int4*  ptrs2 = (const int4*)d_in[3];
    const int4*  ptrs3 = (const int4*)d_in[4];
    // d_in[5] (csr = repeat(arange(M),4)) is implicit in the layout.
    float* out = (float*)d_out;

    float* enc;  cudaGetSymbolAddress((void**)&enc,  g_enc);
    float* bufA; cudaGetSymbolAddress((void**)&bufA, g_bufA);
    float* bufB; cudaGetSymbolAddress((void**)&bufB, g_bufB);

    const int T = 512;
    const int blocksEnc = (N_IN + T - 1) / T;
    const int blocksM   = 148 * 8;   // two waves of 4-resident blocks/SM:
                                     // pipeline + retirement rebalancing

    encode_kernel <<<blocksEnc, T>>>(pos);
    product_kernel<<<blocksM, T>>>(enc,  ptrs0, bufA);
    sum_kernel    <<<blocksM, T>>>(bufA, ptrs1, bufB);
    product_kernel<<<blocksM, T>>>(bufB, ptrs2, bufA);
    sum_kernel    <<<blocksM, T>>>(bufA, ptrs3, out);
}